// round 8
// baseline (speedup 1.0000x reference)
#include <cuda_runtime.h>
#include <cuda_bf16.h>
#include <math.h>
#include <stdint.h>

// ---------------- problem constants ----------------
#define BSZ   4096
#define FDIM  2048
#define KC    64
#define DD    8
#define NTOT  1024          // K * 2 * D
#define NPAIR 2080
#define NTILE 528           // 32*33/2 2x2 pair-tiles

// ---------------- GEMM config (bf16x3 split, mma.sync HMMA) ----------------
#define KEXP    6144        // logical K after 3-way split
#define KSTORE  4096        // physical K stored ([hi|lo]); region remap in loader
#define TM      128
#define TN      128
#define BK      64
#define NS      (KEXP / BK) // 96
#define STAGES  3
#define GT      128         // 4 warps; warp tile 64x64
#define ROWP    72          // padded row length in bf16 (144B: ldmatrix conflict-free)
#define ATILE_B (TM * ROWP * 2)          // 18432 bytes
#define STAGE_B (2 * ATILE_B)            // 36864 bytes
#define SMEM_B  (STAGES * STAGE_B)       // 110592 bytes

// (ln2/2)^8 : folds the 0.5*ln2 per-dim scale of side = 0.5*ln2*log2(1+E)
#define C8     2.0814397e-4f
#define C1EXP  (-14.4269504089f)   // -10 * log2(e)
#define C2EXP  (2.8853900818f)     //   2 * log2(e)

// ---------------- scratch ----------------
__device__ __nv_bfloat16 g_A[(size_t)BSZ * KSTORE];   // [4096][4096] = [Ahi|Alo]
__device__ __nv_bfloat16 g_Bm[(size_t)NTOT * KSTORE]; // [1024][4096] = [Whi|Wlo]
__device__ float g_theta[(size_t)BSZ * NTOT];

// ---------------- PTX helpers ----------------
__device__ __forceinline__ uint32_t smem_u32(const void* p) {
    uint32_t a;
    asm("{ .reg .u64 t; cvta.to.shared.u64 t, %1; cvt.u32.u64 %0, t; }"
        : "=r"(a) : "l"(p));
    return a;
}
__device__ __forceinline__ void cp_async16(uint32_t d, const void* s) {
    asm volatile("cp.async.cg.shared.global [%0], [%1], 16;" :: "r"(d), "l"(s));
}
#define CP_COMMIT() asm volatile("cp.async.commit_group;" ::: "memory")
template <int N> __device__ __forceinline__ void cp_wait() {
    asm volatile("cp.async.wait_group %0;" :: "n"(N) : "memory");
}
__device__ __forceinline__ void ldsm4(uint32_t* r, uint32_t addr) {
    asm volatile("ldmatrix.sync.aligned.m8n8.x4.shared.b16 {%0,%1,%2,%3}, [%4];"
                 : "=r"(r[0]), "=r"(r[1]), "=r"(r[2]), "=r"(r[3]) : "r"(addr));
}
__device__ __forceinline__ void mma16816(float* c, const uint32_t* a, const uint32_t* b) {
    asm volatile(
        "mma.sync.aligned.m16n8k16.row.col.f32.bf16.bf16.f32 "
        "{%0,%1,%2,%3}, {%4,%5,%6,%7}, {%8,%9}, {%0,%1,%2,%3};"
        : "+f"(c[0]), "+f"(c[1]), "+f"(c[2]), "+f"(c[3])
        : "r"(a[0]), "r"(a[1]), "r"(a[2]), "r"(a[3]), "r"(b[0]), "r"(b[1]));
}
__device__ __forceinline__ float ex2f(float x) {
    float y; asm("ex2.approx.ftz.f32 %0, %1;" : "=f"(y) : "f"(x)); return y;
}
__device__ __forceinline__ float lg2f(float x) {
    float y; asm("lg2.approx.ftz.f32 %0, %1;" : "=f"(y) : "f"(x)); return y;
}

// ---------------------------------------------------------------------------
// Conversion kernels: store only [hi | lo] halves; loader replays regions.
// Logical A'' = [Ahi | Alo | Ahi], B'' = [Whi | Whi | Wlo].
// ---------------------------------------------------------------------------
__global__ void __launch_bounds__(256) convA_kernel(const float* __restrict__ feat) {
    const int u = blockIdx.x * 256 + threadIdx.x;
    if (u >= BSZ * (FDIM / 4)) return;
    const int m = u >> 9;
    const int f = (u & 511) * 4;

    const float4 v = *reinterpret_cast<const float4*>(&feat[(size_t)m * FDIM + f]);
    union { __nv_bfloat16 h[4]; uint2 q; } Hi, Lo;
    Hi.h[0] = __float2bfloat16_rn(v.x);
    Hi.h[1] = __float2bfloat16_rn(v.y);
    Hi.h[2] = __float2bfloat16_rn(v.z);
    Hi.h[3] = __float2bfloat16_rn(v.w);
    Lo.h[0] = __float2bfloat16_rn(v.x - __bfloat162float(Hi.h[0]));
    Lo.h[1] = __float2bfloat16_rn(v.y - __bfloat162float(Hi.h[1]));
    Lo.h[2] = __float2bfloat16_rn(v.z - __bfloat162float(Hi.h[2]));
    Lo.h[3] = __float2bfloat16_rn(v.w - __bfloat162float(Hi.h[3]));

    __nv_bfloat16* row = &g_A[(size_t)m * KSTORE];
    *reinterpret_cast<uint2*>(&row[f])        = Hi.q;
    *reinterpret_cast<uint2*>(&row[FDIM + f]) = Lo.q;
}

__global__ void __launch_bounds__(256) convB_kernel(const float* __restrict__ Wp) {
    const int u = blockIdx.x * 256 + threadIdx.x;
    if (u >= NTOT * (FDIM / 4)) return;
    const int n = u >> 9;
    const int f = (u & 511) * 4;
    const int kbox = n >> 4;
    const int dd   = n & 15;

    union { __nv_bfloat16 h[4]; uint2 q; } Hi, Lo;
#pragma unroll
    for (int r = 0; r < 4; r++) {
        const float w = Wp[((size_t)kbox * FDIM + (f + r)) * 16 + dd];
        Hi.h[r] = __float2bfloat16_rn(w);
        Lo.h[r] = __float2bfloat16_rn(w - __bfloat162float(Hi.h[r]));
    }
    __nv_bfloat16* row = &g_Bm[(size_t)n * KSTORE];
    *reinterpret_cast<uint2*>(&row[f])        = Hi.q;
    *reinterpret_cast<uint2*>(&row[FDIM + f]) = Lo.q;
}

// ---------------------------------------------------------------------------
// HMMA GEMM: theta = A'' . B''^T + bp.
// 128x128 CTA tile, BK=64, 3-stage cp.async, 4 warps of 64x64.
// ---------------------------------------------------------------------------
__device__ __forceinline__ void load_stage(int tid, int t, uint32_t sb,
                                           const __nv_bfloat16* Ab,
                                           const __nv_bfloat16* Bb) {
    const int k0 = t * BK;
    const int ksA = (k0 < 2 * FDIM) ? k0 : k0 - 2 * FDIM;  // region 2 -> Ahi
    const int ksB = (k0 < FDIM) ? k0 : k0 - FDIM;          // regions 1,2 -> Whi,Wlo
    const uint32_t stage = sb + (uint32_t)((t % STAGES) * STAGE_B);
#pragma unroll
    for (int i = 0; i < 16; i++) {
        const int c = tid + i * GT;          // 0..2047 chunks of 16B
        if (c < 1024) {                      // A: 128 rows x 8 chunks
            const int row = c >> 3, seg = c & 7;
            cp_async16(stage + (uint32_t)(row * (ROWP * 2) + seg * 16),
                       Ab + (size_t)row * KSTORE + ksA + seg * 8);
        } else {                             // B: 128 rows x 8 chunks
            const int cc = c - 1024;
            const int row = cc >> 3, seg = cc & 7;
            cp_async16(stage + (uint32_t)(ATILE_B + row * (ROWP * 2) + seg * 16),
                       Bb + (size_t)row * KSTORE + ksB + seg * 8);
        }
    }
}

__global__ void __launch_bounds__(GT, 2) gemm_hmma(const float* __restrict__ bp) {
    extern __shared__ char smem[];
    const uint32_t sb = smem_u32(smem);
    const int tid  = threadIdx.x;
    const int wid  = tid >> 5;
    const int lane = tid & 31;
    const int row0 = blockIdx.y * TM;
    const int col0 = blockIdx.x * TN;
    const int m0w  = (wid & 1) * 64;     // warp M offset
    const int n0w  = (wid >> 1) * 64;    // warp N offset

    const __nv_bfloat16* Ab = g_A  + (size_t)row0 * KSTORE;
    const __nv_bfloat16* Bb = g_Bm + (size_t)col0 * KSTORE;

    float c[4][8][4];                    // 4 m-frags x 8 n-frags x 4 accum
#pragma unroll
    for (int mt = 0; mt < 4; mt++)
#pragma unroll
        for (int nt = 0; nt < 8; nt++)
#pragma unroll
            for (int r = 0; r < 4; r++) c[mt][nt][r] = 0.0f;

    const int a_row = lane & 15;
    const int a_col = (lane >> 4) * 8;
    const int b_row = (lane & 7) + ((lane >> 4) & 1) * 8;
    const int b_col = ((lane >> 3) & 1) * 8;

    load_stage(tid, 0, sb, Ab, Bb); CP_COMMIT();
    load_stage(tid, 1, sb, Ab, Bb); CP_COMMIT();

    for (int s = 0; s < NS; s++) {
        cp_wait<STAGES - 2>();
        __syncthreads();
        if (s + STAGES - 1 < NS) load_stage(tid, s + STAGES - 1, sb, Ab, Bb);
        CP_COMMIT();

        const uint32_t sA  = sb + (uint32_t)((s % STAGES) * STAGE_B);
        const uint32_t sBm = sA + ATILE_B;
#pragma unroll
        for (int kk = 0; kk < BK; kk += 16) {
            uint32_t afr[4][4];
            uint32_t bfr[8][2];
#pragma unroll
            for (int mt = 0; mt < 4; mt++)
                ldsm4(afr[mt],
                      sA + (uint32_t)(((m0w + mt * 16 + a_row) * ROWP + kk + a_col) * 2));
#pragma unroll
            for (int np = 0; np < 4; np++) {
                uint32_t q[4];
                ldsm4(q, sBm + (uint32_t)(((n0w + np * 16 + b_row) * ROWP + kk + b_col) * 2));
                bfr[np * 2 + 0][0] = q[0]; bfr[np * 2 + 0][1] = q[1];
                bfr[np * 2 + 1][0] = q[2]; bfr[np * 2 + 1][1] = q[3];
            }
#pragma unroll
            for (int mt = 0; mt < 4; mt++)
#pragma unroll
                for (int nt = 0; nt < 8; nt++)
                    mma16816(c[mt][nt], afr[mt], bfr[nt]);
        }
    }

    const int er = lane >> 2;
    const int ec = (lane & 3) * 2;
#pragma unroll
    for (int mt = 0; mt < 4; mt++) {
#pragma unroll
        for (int nt = 0; nt < 8; nt++) {
            const int m = row0 + m0w + mt * 16 + er;
            const int n = col0 + n0w + nt * 8 + ec;
            const float b0 = __ldg(&bp[n]);
            const float b1 = __ldg(&bp[n + 1]);
            *reinterpret_cast<float2*>(&g_theta[(size_t)m * NTOT + n]) =
                make_float2(c[mt][nt][0] + b0, c[mt][nt][1] + b1);
            *reinterpret_cast<float2*>(&g_theta[(size_t)(m + 8) * NTOT + n]) =
                make_float2(c[mt][nt][2] + b0, c[mt][nt][3] + b1);
        }
    }
}

// ---------------------------------------------------------------------------
// Fused pair kernel: one block per b. (unchanged from R7)
// ---------------------------------------------------------------------------
__device__ __forceinline__ float sp_fast(float x) {
    return fmaxf(x, 0.0f) + __logf(1.0f + __expf(-fabsf(x)));
}
__device__ __forceinline__ int tri_S(int i) { return (i * (129 - i)) >> 1; }

__device__ __forceinline__ float dim1(float zi, float Zi, float zj, float Zj) {
    const float mz = fmaxf(zi, zj);
    const float mZ = fminf(Zi, Zj);
    const float u  = ex2f(C1EXP * fabsf(zi - zj));
    const float v  = ex2f(C1EXP * fabsf(Zi - Zj));
    const float L2 = lg2f((1.0f + u) * (1.0f + v));
    const float E  = ex2f(fmaf(mZ - mz, C2EXP, -0.2f * L2));
    return lg2f(1.0f + E);
}
__device__ __forceinline__ float quad(float4 zi, float4 Zi, float4 zj, float4 Zj) {
    return dim1(zi.x, Zi.x, zj.x, Zj.x) * dim1(zi.y, Zi.y, zj.y, Zj.y)
         * dim1(zi.z, Zi.z, zj.z, Zj.z) * dim1(zi.w, Zi.w, zj.w, Zj.w);
}
__device__ __forceinline__ float pairp(const float4* bi, const float4* bj) {
    return quad(bi[0], bi[2], bj[0], bj[2]) * quad(bi[1], bi[3], bj[1], bj[3]);
}

__global__ void __launch_bounds__(256) pair_kernel(const float* __restrict__ Wprob,
                                                   const float* __restrict__ bprob,
                                                   const float* __restrict__ Wrel,
                                                   const float* __restrict__ Wbox,
                                                   const float* __restrict__ bbox,
                                                   const float* __restrict__ brel,
                                                   float* __restrict__ out_concept,
                                                   float* __restrict__ out_cond,
                                                   float* __restrict__ out_task) {
    __shared__ float4 zZ4q[KC * 5];
    __shared__ float elvbC[KC];
    __shared__ float p_sh[KC];
    __shared__ float wrel_sh[KC * KC];
    __shared__ float wbox_sh[KC * 16];
    __shared__ float prod_sh[NPAIR];
    __shared__ float side_tmp[KC * DD];
    __shared__ float dot_tmp[KC * DD];
    __shared__ float red[256];

    const int b   = blockIdx.x;
    const int tid = threadIdx.x;
    float* zZf = reinterpret_cast<float*>(zZ4q);

    for (int idx = tid; idx < KC * KC; idx += 256) wrel_sh[idx] = Wrel[idx];
    for (int idx = tid; idx < KC * 16; idx += 256) wbox_sh[idx] = Wbox[idx];

    for (int u = tid; u < KC * DD; u += 256) {
        const int k = u >> 3, d = u & 7;
        const float* th = &g_theta[(size_t)b * NTOT + k * 16];
        const float z = th[d];
        const float Z = z + sp_fast(th[8 + d]);
        zZf[k * 20 + d]     = z;
        zZf[k * 20 + 8 + d] = Z;
        side_tmp[u] = 0.5f * sp_fast(2.0f * (Z - z));
        dot_tmp[u]  = z * __ldg(&Wprob[k * 16 + d]) + Z * __ldg(&Wprob[k * 16 + 8 + d]);
    }
    __syncthreads();

    if (tid < KC) {
        float pb = 1.0f;
        float lg = __ldg(&bprob[tid]);
#pragma unroll
        for (int d = 0; d < 8; d++) {
            pb *= side_tmp[tid * 8 + d];
            lg += dot_tmp[tid * 8 + d];
        }
        elvbC[tid] = C8 / pb;
        const float p = 1.0f / (1.0f + __expf(-lg));
        p_sh[tid] = p;
        out_concept[b * KC + tid] = p;
    }
    __syncthreads();

    for (int T = tid; T < NTILE; T += 256) {
        const int tt = T / 33;
        const int s  = T - tt * 33;
        int b2 = s + tt + 1;
        if (b2 >= 33) b2 -= 33;
        const int lo = min(s, b2), hi = max(s, b2);
        const int i0 = lo * 2;
        const int j0 = (hi - 1) * 2;

        float4 BI0[4], BI1[4], BJ0[4], BJ1[4];
#pragma unroll
        for (int r = 0; r < 4; r++) {
            BI0[r] = zZ4q[(i0 + 0) * 5 + r];
            BI1[r] = zZ4q[(i0 + 1) * 5 + r];
            BJ0[r] = zZ4q[(j0 + 0) * 5 + r];
            BJ1[r] = zZ4q[(j0 + 1) * 5 + r];
        }

        const float p00 = pairp(BI0, BJ0);
        const float p01 = pairp(BI0, BJ1);
        const float p11 = pairp(BI1, BJ1);

        const int q0 = tri_S(i0) + (j0 - i0);
        const int q1 = tri_S(i0 + 1) + (j0 - i0 - 1);
        prod_sh[q0]     = p00;
        prod_sh[q0 + 1] = p01;
        prod_sh[q1 + 1] = p11;
        if (i0 < j0) {
            prod_sh[q1] = pairp(BI1, BJ0);
        }
    }
    __syncthreads();

    float accrel = 0.0f;
#pragma unroll
    for (int g = 0; g < 4; g++) {
        const int idx = g * 1024 + tid * 4;
        const int i  = idx >> 6;
        const int jb = idx & 63;
        float4 cd;
        float* cdp = &cd.x;
#pragma unroll
        for (int r = 0; r < 4; r++) {
            const int j = jb + r;
            const int a = min(i, j), bq = max(i, j);
            const int q = tri_S(a) + (bq - a);
            float cc = prod_sh[q] * elvbC[j];
            cc = fminf(fmaxf(cc, 1e-6f), 1.0f - 1e-6f);
            cdp[r] = cc;
            accrel = fmaf(cc, wrel_sh[idx + r], accrel);
        }
        *reinterpret_cast<float4*>(&out_cond[(size_t)b * (KC * KC) + idx]) = cd;
    }

    red[tid] = accrel;
    __syncthreads();
    for (int s = 128; s > 0; s >>= 1) {
        if (tid < s) red[tid] += red[tid + s];
        __syncthreads();
    }
    const float reldot = red[0];
    __syncthreads();

    if (tid < KC) {
        float s = 0.0f;
#pragma unroll
        for (int d = 0; d < 8; d++) {
            s = fmaf(zZf[tid * 20 + d],     wbox_sh[tid * 16 + d],     s);
            s = fmaf(zZf[tid * 20 + 8 + d], wbox_sh[tid * 16 + 8 + d], s);
        }
        red[tid] = s * p_sh[tid];
    }
    __syncthreads();
    for (int s = 32; s > 0; s >>= 1) {
        if (tid < s) red[tid] += red[tid + s];
        __syncthreads();
    }

    if (tid == 0) {
        const float logit = red[0] + bbox[0] + reldot + brel[0];
        out_task[b] = 1.0f / (1.0f + expf(-logit));
    }
}

// ---------------------------------------------------------------------------
extern "C" void kernel_launch(void* const* d_in, const int* in_sizes, int n_in,
                              void* d_out, int out_size) {
    const float* features = (const float*)d_in[0];
    const float* Wp       = (const float*)d_in[1];
    const float* bp       = (const float*)d_in[2];
    const float* Wprob    = (const float*)d_in[3];
    const float* bprob    = (const float*)d_in[4];
    const float* Wbox     = (const float*)d_in[5];
    const float* bbox     = (const float*)d_in[6];
    const float* Wrel     = (const float*)d_in[7];
    const float* brel     = (const float*)d_in[8];

    float* out         = (float*)d_out;
    float* out_task    = out;
    float* out_concept = out + BSZ;
    float* out_cond    = out + BSZ + BSZ * KC;

    cudaFuncSetAttribute(gemm_hmma, cudaFuncAttributeMaxDynamicSharedMemorySize, SMEM_B);

    convA_kernel<<<(BSZ * (FDIM / 4) + 255) / 256, 256>>>(features);
    convB_kernel<<<(NTOT * (FDIM / 4) + 255) / 256, 256>>>(Wp);
    gemm_hmma<<<dim3(NTOT / TN, BSZ / TM), GT, SMEM_B>>>(bp);
    pair_kernel<<<BSZ, 256>>>(Wprob, bprob, Wrel, Wbox, bbox, brel,
                              out_concept, out_cond, out_task);
}

// round 9
// speedup vs baseline: 1.0131x; 1.0131x over previous
#include <cuda_runtime.h>
#include <cuda_bf16.h>
#include <math.h>
#include <stdint.h>

// ---------------- problem constants ----------------
#define BSZ   4096
#define FDIM  2048
#define KC    64
#define DD    8
#define NTOT  1024          // K * 2 * D
#define NPAIR 2080
#define NTILE 528           // 32*33/2 2x2 pair-tiles

// ---------------- GEMM config (bf16x3 split, mma.sync HMMA) ----------------
#define KEXP    6144        // logical K after 3-way split
#define KSTORE  4096        // physical K stored ([hi|lo]); region remap in loader
#define TM      128
#define TN      128
#define BK      64
#define NS      (KEXP / BK) // 96
#define STAGES  3
#define GT      256         // 8 warps; warp tile 64x32
#define ROWP    72          // padded row length in bf16 (144B: ldmatrix conflict-free)
#define ATILE_B (TM * ROWP * 2)          // 18432 bytes
#define STAGE_B (2 * ATILE_B)            // 36864 bytes
#define SMEM_B  (STAGES * STAGE_B)       // 110592 bytes

// (ln2/2)^8 : folds the 0.5*ln2 per-dim scale of side = 0.5*ln2*log2(1+E)
#define C8     2.0814397e-4f
#define C1EXP  (-14.4269504089f)   // -10 * log2(e)
#define C2EXP  (2.8853900818f)     //   2 * log2(e)

// ---------------- scratch ----------------
__device__ __nv_bfloat16 g_A[(size_t)BSZ * KSTORE];   // [4096][4096] = [Ahi|Alo]
__device__ __nv_bfloat16 g_Bm[(size_t)NTOT * KSTORE]; // [1024][4096] = [Whi|Wlo]
__device__ float g_theta[(size_t)BSZ * NTOT];

// ---------------- PTX helpers ----------------
__device__ __forceinline__ uint32_t smem_u32(const void* p) {
    uint32_t a;
    asm("{ .reg .u64 t; cvta.to.shared.u64 t, %1; cvt.u32.u64 %0, t; }"
        : "=r"(a) : "l"(p));
    return a;
}
__device__ __forceinline__ void cp_async16(uint32_t d, const void* s) {
    asm volatile("cp.async.cg.shared.global [%0], [%1], 16;" :: "r"(d), "l"(s));
}
#define CP_COMMIT() asm volatile("cp.async.commit_group;" ::: "memory")
template <int N> __device__ __forceinline__ void cp_wait() {
    asm volatile("cp.async.wait_group %0;" :: "n"(N) : "memory");
}
__device__ __forceinline__ void ldsm4(uint32_t* r, uint32_t addr) {
    asm volatile("ldmatrix.sync.aligned.m8n8.x4.shared.b16 {%0,%1,%2,%3}, [%4];"
                 : "=r"(r[0]), "=r"(r[1]), "=r"(r[2]), "=r"(r[3]) : "r"(addr));
}
__device__ __forceinline__ void mma16816(float* c, const uint32_t* a, const uint32_t* b) {
    asm volatile(
        "mma.sync.aligned.m16n8k16.row.col.f32.bf16.bf16.f32 "
        "{%0,%1,%2,%3}, {%4,%5,%6,%7}, {%8,%9}, {%0,%1,%2,%3};"
        : "+f"(c[0]), "+f"(c[1]), "+f"(c[2]), "+f"(c[3])
        : "r"(a[0]), "r"(a[1]), "r"(a[2]), "r"(a[3]), "r"(b[0]), "r"(b[1]));
}
__device__ __forceinline__ float ex2f(float x) {
    float y; asm("ex2.approx.ftz.f32 %0, %1;" : "=f"(y) : "f"(x)); return y;
}
__device__ __forceinline__ float lg2f(float x) {
    float y; asm("lg2.approx.ftz.f32 %0, %1;" : "=f"(y) : "f"(x)); return y;
}

// ---------------------------------------------------------------------------
// Conversion kernels: store only [hi | lo] halves; loader replays regions.
// Logical A'' = [Ahi | Alo | Ahi], B'' = [Whi | Whi | Wlo].
// ---------------------------------------------------------------------------
__global__ void __launch_bounds__(256) convA_kernel(const float* __restrict__ feat) {
    const int u = blockIdx.x * 256 + threadIdx.x;
    if (u >= BSZ * (FDIM / 4)) return;
    const int m = u >> 9;
    const int f = (u & 511) * 4;

    const float4 v = *reinterpret_cast<const float4*>(&feat[(size_t)m * FDIM + f]);
    union { __nv_bfloat16 h[4]; uint2 q; } Hi, Lo;
    Hi.h[0] = __float2bfloat16_rn(v.x);
    Hi.h[1] = __float2bfloat16_rn(v.y);
    Hi.h[2] = __float2bfloat16_rn(v.z);
    Hi.h[3] = __float2bfloat16_rn(v.w);
    Lo.h[0] = __float2bfloat16_rn(v.x - __bfloat162float(Hi.h[0]));
    Lo.h[1] = __float2bfloat16_rn(v.y - __bfloat162float(Hi.h[1]));
    Lo.h[2] = __float2bfloat16_rn(v.z - __bfloat162float(Hi.h[2]));
    Lo.h[3] = __float2bfloat16_rn(v.w - __bfloat162float(Hi.h[3]));

    __nv_bfloat16* row = &g_A[(size_t)m * KSTORE];
    *reinterpret_cast<uint2*>(&row[f])        = Hi.q;
    *reinterpret_cast<uint2*>(&row[FDIM + f]) = Lo.q;
}

__global__ void __launch_bounds__(256) convB_kernel(const float* __restrict__ Wp) {
    const int u = blockIdx.x * 256 + threadIdx.x;
    if (u >= NTOT * (FDIM / 4)) return;
    const int n = u >> 9;
    const int f = (u & 511) * 4;
    const int kbox = n >> 4;
    const int dd   = n & 15;

    union { __nv_bfloat16 h[4]; uint2 q; } Hi, Lo;
#pragma unroll
    for (int r = 0; r < 4; r++) {
        const float w = Wp[((size_t)kbox * FDIM + (f + r)) * 16 + dd];
        Hi.h[r] = __float2bfloat16_rn(w);
        Lo.h[r] = __float2bfloat16_rn(w - __bfloat162float(Hi.h[r]));
    }
    __nv_bfloat16* row = &g_Bm[(size_t)n * KSTORE];
    *reinterpret_cast<uint2*>(&row[f])        = Hi.q;
    *reinterpret_cast<uint2*>(&row[FDIM + f]) = Lo.q;
}

// ---------------------------------------------------------------------------
// HMMA GEMM: theta = A'' . B''^T + bp.
// 128x128 CTA tile, BK=64, 3-stage cp.async, 8 warps of 64x32,
// register double-buffered fragments across k16 groups.
// ---------------------------------------------------------------------------
__device__ __forceinline__ void load_stage(int tid, int t, uint32_t sb,
                                           const __nv_bfloat16* Ab,
                                           const __nv_bfloat16* Bb) {
    const int k0 = t * BK;
    const int ksA = (k0 < 2 * FDIM) ? k0 : k0 - 2 * FDIM;  // region 2 -> Ahi
    const int ksB = (k0 < FDIM) ? k0 : k0 - FDIM;          // regions 1,2 -> Whi,Wlo
    const uint32_t stage = sb + (uint32_t)((t % STAGES) * STAGE_B);
#pragma unroll
    for (int i = 0; i < 8; i++) {
        const int c = tid + i * GT;          // 0..2047 chunks of 16B
        if (c < 1024) {                      // A: 128 rows x 8 chunks
            const int row = c >> 3, seg = c & 7;
            cp_async16(stage + (uint32_t)(row * (ROWP * 2) + seg * 16),
                       Ab + (size_t)row * KSTORE + ksA + seg * 8);
        } else {                             // B: 128 rows x 8 chunks
            const int cc = c - 1024;
            const int row = cc >> 3, seg = cc & 7;
            cp_async16(stage + (uint32_t)(ATILE_B + row * (ROWP * 2) + seg * 16),
                       Bb + (size_t)row * KSTORE + ksB + seg * 8);
        }
    }
}

__device__ __forceinline__ void ldA_group(uint32_t afr[4][4], uint32_t sA, int kk,
                                          int m0w, int a_row, int a_col) {
#pragma unroll
    for (int mt = 0; mt < 4; mt++)
        ldsm4(afr[mt],
              sA + (uint32_t)(((m0w + mt * 16 + a_row) * ROWP + kk + a_col) * 2));
}
__device__ __forceinline__ void ldB_group(uint32_t bfr[4][2], uint32_t sBm, int kk,
                                          int n0w, int b_row, int b_col) {
#pragma unroll
    for (int np = 0; np < 2; np++) {
        uint32_t q[4];
        ldsm4(q, sBm + (uint32_t)(((n0w + np * 16 + b_row) * ROWP + kk + b_col) * 2));
        bfr[np * 2 + 0][0] = q[0]; bfr[np * 2 + 0][1] = q[1];
        bfr[np * 2 + 1][0] = q[2]; bfr[np * 2 + 1][1] = q[3];
    }
}

__global__ void __launch_bounds__(GT, 2) gemm_hmma(const float* __restrict__ bp) {
    extern __shared__ char smem[];
    const uint32_t sb = smem_u32(smem);
    const int tid  = threadIdx.x;
    const int wid  = tid >> 5;
    const int lane = tid & 31;
    const int row0 = blockIdx.y * TM;
    const int col0 = blockIdx.x * TN;
    const int m0w  = (wid >> 2) * 64;
    const int n0w  = (wid & 3) * 32;

    const __nv_bfloat16* Ab = g_A  + (size_t)row0 * KSTORE;
    const __nv_bfloat16* Bb = g_Bm + (size_t)col0 * KSTORE;

    float c[4][4][4];
#pragma unroll
    for (int mt = 0; mt < 4; mt++)
#pragma unroll
        for (int nt = 0; nt < 4; nt++)
#pragma unroll
            for (int r = 0; r < 4; r++) c[mt][nt][r] = 0.0f;

    const int a_row = lane & 15;
    const int a_col = (lane >> 4) * 8;
    const int b_row = (lane & 7) + ((lane >> 4) & 1) * 8;
    const int b_col = ((lane >> 3) & 1) * 8;

    load_stage(tid, 0, sb, Ab, Bb); CP_COMMIT();
    load_stage(tid, 1, sb, Ab, Bb); CP_COMMIT();

    uint32_t afr[2][4][4];
    uint32_t bfr[2][4][2];

    for (int s = 0; s < NS; s++) {
        cp_wait<STAGES - 2>();
        __syncthreads();
        if (s + STAGES - 1 < NS) load_stage(tid, s + STAGES - 1, sb, Ab, Bb);
        CP_COMMIT();

        const uint32_t sA  = sb + (uint32_t)((s % STAGES) * STAGE_B);
        const uint32_t sBm = sA + ATILE_B;

        // prefetch k16 group 0
        ldA_group(afr[0], sA, 0, m0w, a_row, a_col);
        ldB_group(bfr[0], sBm, 0, n0w, b_row, b_col);
#pragma unroll
        for (int kg = 0; kg < 4; kg++) {
            const int cur = kg & 1;
            const int nxt = cur ^ 1;
            if (kg < 3) {   // prefetch next group while MMAs of this group issue
                ldA_group(afr[nxt], sA, (kg + 1) * 16, m0w, a_row, a_col);
                ldB_group(bfr[nxt], sBm, (kg + 1) * 16, n0w, b_row, b_col);
            }
#pragma unroll
            for (int mt = 0; mt < 4; mt++)
#pragma unroll
                for (int nt = 0; nt < 4; nt++)
                    mma16816(c[mt][nt], afr[cur][mt], bfr[cur][nt]);
        }
    }

    const int er = lane >> 2;
    const int ec = (lane & 3) * 2;
#pragma unroll
    for (int mt = 0; mt < 4; mt++) {
#pragma unroll
        for (int nt = 0; nt < 4; nt++) {
            const int m = row0 + m0w + mt * 16 + er;
            const int n = col0 + n0w + nt * 8 + ec;
            const float b0 = __ldg(&bp[n]);
            const float b1 = __ldg(&bp[n + 1]);
            *reinterpret_cast<float2*>(&g_theta[(size_t)m * NTOT + n]) =
                make_float2(c[mt][nt][0] + b0, c[mt][nt][1] + b1);
            *reinterpret_cast<float2*>(&g_theta[(size_t)(m + 8) * NTOT + n]) =
                make_float2(c[mt][nt][2] + b0, c[mt][nt][3] + b1);
        }
    }
}

// ---------------------------------------------------------------------------
// Fused pair kernel: one block per b. (unchanged from R7)
// ---------------------------------------------------------------------------
__device__ __forceinline__ float sp_fast(float x) {
    return fmaxf(x, 0.0f) + __logf(1.0f + __expf(-fabsf(x)));
}
__device__ __forceinline__ int tri_S(int i) { return (i * (129 - i)) >> 1; }

__device__ __forceinline__ float dim1(float zi, float Zi, float zj, float Zj) {
    const float mz = fmaxf(zi, zj);
    const float mZ = fminf(Zi, Zj);
    const float u  = ex2f(C1EXP * fabsf(zi - zj));
    const float v  = ex2f(C1EXP * fabsf(Zi - Zj));
    const float L2 = lg2f((1.0f + u) * (1.0f + v));
    const float E  = ex2f(fmaf(mZ - mz, C2EXP, -0.2f * L2));
    return lg2f(1.0f + E);
}
__device__ __forceinline__ float quad(float4 zi, float4 Zi, float4 zj, float4 Zj) {
    return dim1(zi.x, Zi.x, zj.x, Zj.x) * dim1(zi.y, Zi.y, zj.y, Zj.y)
         * dim1(zi.z, Zi.z, zj.z, Zj.z) * dim1(zi.w, Zi.w, zj.w, Zj.w);
}
__device__ __forceinline__ float pairp(const float4* bi, const float4* bj) {
    return quad(bi[0], bi[2], bj[0], bj[2]) * quad(bi[1], bi[3], bj[1], bj[3]);
}

__global__ void __launch_bounds__(256) pair_kernel(const float* __restrict__ Wprob,
                                                   const float* __restrict__ bprob,
                                                   const float* __restrict__ Wrel,
                                                   const float* __restrict__ Wbox,
                                                   const float* __restrict__ bbox,
                                                   const float* __restrict__ brel,
                                                   float* __restrict__ out_concept,
                                                   float* __restrict__ out_cond,
                                                   float* __restrict__ out_task) {
    __shared__ float4 zZ4q[KC * 5];
    __shared__ float elvbC[KC];
    __shared__ float p_sh[KC];
    __shared__ float wrel_sh[KC * KC];
    __shared__ float wbox_sh[KC * 16];
    __shared__ float prod_sh[NPAIR];
    __shared__ float side_tmp[KC * DD];
    __shared__ float dot_tmp[KC * DD];
    __shared__ float red[256];

    const int b   = blockIdx.x;
    const int tid = threadIdx.x;
    float* zZf = reinterpret_cast<float*>(zZ4q);

    for (int idx = tid; idx < KC * KC; idx += 256) wrel_sh[idx] = Wrel[idx];
    for (int idx = tid; idx < KC * 16; idx += 256) wbox_sh[idx] = Wbox[idx];

    for (int u = tid; u < KC * DD; u += 256) {
        const int k = u >> 3, d = u & 7;
        const float* th = &g_theta[(size_t)b * NTOT + k * 16];
        const float z = th[d];
        const float Z = z + sp_fast(th[8 + d]);
        zZf[k * 20 + d]     = z;
        zZf[k * 20 + 8 + d] = Z;
        side_tmp[u] = 0.5f * sp_fast(2.0f * (Z - z));
        dot_tmp[u]  = z * __ldg(&Wprob[k * 16 + d]) + Z * __ldg(&Wprob[k * 16 + 8 + d]);
    }
    __syncthreads();

    if (tid < KC) {
        float pb = 1.0f;
        float lg = __ldg(&bprob[tid]);
#pragma unroll
        for (int d = 0; d < 8; d++) {
            pb *= side_tmp[tid * 8 + d];
            lg += dot_tmp[tid * 8 + d];
        }
        elvbC[tid] = C8 / pb;
        const float p = 1.0f / (1.0f + __expf(-lg));
        p_sh[tid] = p;
        out_concept[b * KC + tid] = p;
    }
    __syncthreads();

    for (int T = tid; T < NTILE; T += 256) {
        const int tt = T / 33;
        const int s  = T - tt * 33;
        int b2 = s + tt + 1;
        if (b2 >= 33) b2 -= 33;
        const int lo = min(s, b2), hi = max(s, b2);
        const int i0 = lo * 2;
        const int j0 = (hi - 1) * 2;

        float4 BI0[4], BI1[4], BJ0[4], BJ1[4];
#pragma unroll
        for (int r = 0; r < 4; r++) {
            BI0[r] = zZ4q[(i0 + 0) * 5 + r];
            BI1[r] = zZ4q[(i0 + 1) * 5 + r];
            BJ0[r] = zZ4q[(j0 + 0) * 5 + r];
            BJ1[r] = zZ4q[(j0 + 1) * 5 + r];
        }

        const float p00 = pairp(BI0, BJ0);
        const float p01 = pairp(BI0, BJ1);
        const float p11 = pairp(BI1, BJ1);

        const int q0 = tri_S(i0) + (j0 - i0);
        const int q1 = tri_S(i0 + 1) + (j0 - i0 - 1);
        prod_sh[q0]     = p00;
        prod_sh[q0 + 1] = p01;
        prod_sh[q1 + 1] = p11;
        if (i0 < j0) {
            prod_sh[q1] = pairp(BI1, BJ0);
        }
    }
    __syncthreads();

    float accrel = 0.0f;
#pragma unroll
    for (int g = 0; g < 4; g++) {
        const int idx = g * 1024 + tid * 4;
        const int i  = idx >> 6;
        const int jb = idx & 63;
        float4 cd;
        float* cdp = &cd.x;
#pragma unroll
        for (int r = 0; r < 4; r++) {
            const int j = jb + r;
            const int a = min(i, j), bq = max(i, j);
            const int q = tri_S(a) + (bq - a);
            float cc = prod_sh[q] * elvbC[j];
            cc = fminf(fmaxf(cc, 1e-6f), 1.0f - 1e-6f);
            cdp[r] = cc;
            accrel = fmaf(cc, wrel_sh[idx + r], accrel);
        }
        *reinterpret_cast<float4*>(&out_cond[(size_t)b * (KC * KC) + idx]) = cd;
    }

    red[tid] = accrel;
    __syncthreads();
    for (int s = 128; s > 0; s >>= 1) {
        if (tid < s) red[tid] += red[tid + s];
        __syncthreads();
    }
    const float reldot = red[0];
    __syncthreads();

    if (tid < KC) {
        float s = 0.0f;
#pragma unroll
        for (int d = 0; d < 8; d++) {
            s = fmaf(zZf[tid * 20 + d],     wbox_sh[tid * 16 + d],     s);
            s = fmaf(zZf[tid * 20 + 8 + d], wbox_sh[tid * 16 + 8 + d], s);
        }
        red[tid] = s * p_sh[tid];
    }
    __syncthreads();
    for (int s = 32; s > 0; s >>= 1) {
        if (tid < s) red[tid] += red[tid + s];
        __syncthreads();
    }

    if (tid == 0) {
        const float logit = red[0] + bbox[0] + reldot + brel[0];
        out_task[b] = 1.0f / (1.0f + expf(-logit));
    }
}

// ---------------------------------------------------------------------------
extern "C" void kernel_launch(void* const* d_in, const int* in_sizes, int n_in,
                              void* d_out, int out_size) {
    const float* features = (const float*)d_in[0];
    const float* Wp       = (const float*)d_in[1];
    const float* bp       = (const float*)d_in[2];
    const float* Wprob    = (const float*)d_in[3];
    const float* bprob    = (const float*)d_in[4];
    const float* Wbox     = (const float*)d_in[5];
    const float* bbox     = (const float*)d_in[6];
    const float* Wrel     = (const float*)d_in[7];
    const float* brel     = (const float*)d_in[8];

    float* out         = (float*)d_out;
    float* out_task    = out;
    float* out_concept = out + BSZ;
    float* out_cond    = out + BSZ + BSZ * KC;

    cudaFuncSetAttribute(gemm_hmma, cudaFuncAttributeMaxDynamicSharedMemorySize, SMEM_B);

    convA_kernel<<<(BSZ * (FDIM / 4) + 255) / 256, 256>>>(features);
    convB_kernel<<<(NTOT * (FDIM / 4) + 255) / 256, 256>>>(Wp);
    gemm_hmma<<<dim3(NTOT / TN, BSZ / TM), GT, SMEM_B>>>(bp);
    pair_kernel<<<BSZ, 256>>>(Wprob, bprob, Wrel, Wbox, bbox, brel,
                              out_concept, out_cond, out_task);
}

// round 10
// speedup vs baseline: 1.2873x; 1.2707x over previous
#include <cuda_runtime.h>
#include <cuda_fp16.h>
#include <math.h>
#include <stdint.h>

// ---------------- problem constants ----------------
#define BSZ   4096
#define FDIM  2048
#define KC    64
#define DD    8
#define NTOT  1024          // K * 2 * D
#define NPAIR 2080
#define NTILE 528           // 32*33/2 2x2 pair-tiles

// ---------------- GEMM config (fp16x2 split, mma.sync HMMA) ----------------
// A'' = [Ahi | Alo] (fp16), B'' = [Whi | Whi] (fp16). Dropped term A*Wlo ~ 2^-11.8.
#define KEXP    4096        // logical K after 2-way split
#define KA      4096        // physical A K ([hi|lo])
#define KB      2048        // physical B K (hi only; replayed for both halves)
#define TM      128
#define TN      128
#define BK      64
#define NS      (KEXP / BK) // 64
#define STAGES  3
#define GT      256         // 8 warps; warp tile 64x32
#define ROWP    72          // padded row length in fp16 (144B: ldmatrix conflict-free)
#define ATILE_B (TM * ROWP * 2)          // 18432 bytes
#define STAGE_B (2 * ATILE_B)            // 36864 bytes
#define SMEM_B  (STAGES * STAGE_B)       // 110592 bytes

// (ln2/2)^8 : folds the 0.5*ln2 per-dim scale of side = 0.5*ln2*log2(1+E)
#define C8     2.0814397e-4f
#define C1EXP  (-14.4269504089f)   // -10 * log2(e)
#define C2EXP  (2.8853900818f)     //   2 * log2(e)

// ---------------- scratch ----------------
__device__ __half g_A[(size_t)BSZ * KA];    // [4096][4096] = [Ahi|Alo]
__device__ __half g_Bm[(size_t)NTOT * KB];  // [1024][2048] = [Whi]
__device__ float g_theta[(size_t)BSZ * NTOT];

// ---------------- PTX helpers ----------------
__device__ __forceinline__ uint32_t smem_u32(const void* p) {
    uint32_t a;
    asm("{ .reg .u64 t; cvta.to.shared.u64 t, %1; cvt.u32.u64 %0, t; }"
        : "=r"(a) : "l"(p));
    return a;
}
__device__ __forceinline__ void cp_async16(uint32_t d, const void* s) {
    asm volatile("cp.async.cg.shared.global [%0], [%1], 16;" :: "r"(d), "l"(s));
}
#define CP_COMMIT() asm volatile("cp.async.commit_group;" ::: "memory")
template <int N> __device__ __forceinline__ void cp_wait() {
    asm volatile("cp.async.wait_group %0;" :: "n"(N) : "memory");
}
__device__ __forceinline__ void ldsm4(uint32_t* r, uint32_t addr) {
    asm volatile("ldmatrix.sync.aligned.m8n8.x4.shared.b16 {%0,%1,%2,%3}, [%4];"
                 : "=r"(r[0]), "=r"(r[1]), "=r"(r[2]), "=r"(r[3]) : "r"(addr));
}
__device__ __forceinline__ void mma16816(float* c, const uint32_t* a, const uint32_t* b) {
    asm volatile(
        "mma.sync.aligned.m16n8k16.row.col.f32.f16.f16.f32 "
        "{%0,%1,%2,%3}, {%4,%5,%6,%7}, {%8,%9}, {%0,%1,%2,%3};"
        : "+f"(c[0]), "+f"(c[1]), "+f"(c[2]), "+f"(c[3])
        : "r"(a[0]), "r"(a[1]), "r"(a[2]), "r"(a[3]), "r"(b[0]), "r"(b[1]));
}
__device__ __forceinline__ float ex2f(float x) {
    float y; asm("ex2.approx.ftz.f32 %0, %1;" : "=f"(y) : "f"(x)); return y;
}
__device__ __forceinline__ float lg2f(float x) {
    float y; asm("lg2.approx.ftz.f32 %0, %1;" : "=f"(y) : "f"(x)); return y;
}

// ---------------------------------------------------------------------------
// Conversion kernels.
// ---------------------------------------------------------------------------
__global__ void __launch_bounds__(256) convA_kernel(const float* __restrict__ feat) {
    const int u = blockIdx.x * 256 + threadIdx.x;
    if (u >= BSZ * (FDIM / 4)) return;
    const int m = u >> 9;
    const int f = (u & 511) * 4;

    const float4 v = *reinterpret_cast<const float4*>(&feat[(size_t)m * FDIM + f]);
    union { __half h[4]; uint2 q; } Hi, Lo;
    Hi.h[0] = __float2half_rn(v.x);
    Hi.h[1] = __float2half_rn(v.y);
    Hi.h[2] = __float2half_rn(v.z);
    Hi.h[3] = __float2half_rn(v.w);
    Lo.h[0] = __float2half_rn(v.x - __half2float(Hi.h[0]));
    Lo.h[1] = __float2half_rn(v.y - __half2float(Hi.h[1]));
    Lo.h[2] = __float2half_rn(v.z - __half2float(Hi.h[2]));
    Lo.h[3] = __float2half_rn(v.w - __half2float(Hi.h[3]));

    __half* row = &g_A[(size_t)m * KA];
    *reinterpret_cast<uint2*>(&row[f])        = Hi.q;
    *reinterpret_cast<uint2*>(&row[FDIM + f]) = Lo.q;
}

__global__ void __launch_bounds__(256) convB_kernel(const float* __restrict__ Wp) {
    const int u = blockIdx.x * 256 + threadIdx.x;
    if (u >= NTOT * (FDIM / 4)) return;
    const int n = u >> 9;
    const int f = (u & 511) * 4;
    const int kbox = n >> 4;
    const int dd   = n & 15;

    union { __half h[4]; uint2 q; } Hi;
#pragma unroll
    for (int r = 0; r < 4; r++) {
        const float w = Wp[((size_t)kbox * FDIM + (f + r)) * 16 + dd];
        Hi.h[r] = __float2half_rn(w);
    }
    *reinterpret_cast<uint2*>(&g_Bm[(size_t)n * KB + f]) = Hi.q;
}

// ---------------------------------------------------------------------------
// HMMA GEMM: theta = A'' . B''^T + bp.
// 128x128 CTA tile, BK=64, 3-stage cp.async, 8 warps of 64x32. (R7 inner loop)
// ---------------------------------------------------------------------------
__device__ __forceinline__ void load_stage(int tid, int t, uint32_t sb,
                                           const __half* Ab,
                                           const __half* Bb) {
    const int k0 = t * BK;
    const int ksB = (k0 < FDIM) ? k0 : k0 - FDIM;   // B hi replayed for lo half
    const uint32_t stage = sb + (uint32_t)((t % STAGES) * STAGE_B);
#pragma unroll
    for (int i = 0; i < 8; i++) {
        const int c = tid + i * GT;          // 0..2047 chunks of 16B
        if (c < 1024) {                      // A: 128 rows x 8 chunks
            const int row = c >> 3, seg = c & 7;
            cp_async16(stage + (uint32_t)(row * (ROWP * 2) + seg * 16),
                       Ab + (size_t)row * KA + k0 + seg * 8);
        } else {                             // B: 128 rows x 8 chunks
            const int cc = c - 1024;
            const int row = cc >> 3, seg = cc & 7;
            cp_async16(stage + (uint32_t)(ATILE_B + row * (ROWP * 2) + seg * 16),
                       Bb + (size_t)row * KB + ksB + seg * 8);
        }
    }
}

__global__ void __launch_bounds__(GT, 2) gemm_hmma(const float* __restrict__ bp) {
    extern __shared__ char smem[];
    const uint32_t sb = smem_u32(smem);
    const int tid  = threadIdx.x;
    const int wid  = tid >> 5;
    const int lane = tid & 31;
    const int row0 = blockIdx.y * TM;
    const int col0 = blockIdx.x * TN;
    const int m0w  = (wid >> 2) * 64;
    const int n0w  = (wid & 3) * 32;

    const __half* Ab = g_A  + (size_t)row0 * KA;
    const __half* Bb = g_Bm + (size_t)col0 * KB;

    float c[4][4][4];
#pragma unroll
    for (int mt = 0; mt < 4; mt++)
#pragma unroll
        for (int nt = 0; nt < 4; nt++)
#pragma unroll
            for (int r = 0; r < 4; r++) c[mt][nt][r] = 0.0f;

    const int a_row = lane & 15;
    const int a_col = (lane >> 4) * 8;
    const int b_row = (lane & 7) + ((lane >> 4) & 1) * 8;
    const int b_col = ((lane >> 3) & 1) * 8;

    load_stage(tid, 0, sb, Ab, Bb); CP_COMMIT();
    load_stage(tid, 1, sb, Ab, Bb); CP_COMMIT();

    for (int s = 0; s < NS; s++) {
        cp_wait<STAGES - 2>();
        __syncthreads();
        if (s + STAGES - 1 < NS) load_stage(tid, s + STAGES - 1, sb, Ab, Bb);
        CP_COMMIT();

        const uint32_t sA  = sb + (uint32_t)((s % STAGES) * STAGE_B);
        const uint32_t sBm = sA + ATILE_B;
#pragma unroll
        for (int kk = 0; kk < BK; kk += 16) {
            uint32_t afr[4][4];
            uint32_t bfr[4][2];
#pragma unroll
            for (int mt = 0; mt < 4; mt++)
                ldsm4(afr[mt],
                      sA + (uint32_t)(((m0w + mt * 16 + a_row) * ROWP + kk + a_col) * 2));
#pragma unroll
            for (int np = 0; np < 2; np++) {
                uint32_t q[4];
                ldsm4(q, sBm + (uint32_t)(((n0w + np * 16 + b_row) * ROWP + kk + b_col) * 2));
                bfr[np * 2 + 0][0] = q[0]; bfr[np * 2 + 0][1] = q[1];
                bfr[np * 2 + 1][0] = q[2]; bfr[np * 2 + 1][1] = q[3];
            }
#pragma unroll
            for (int mt = 0; mt < 4; mt++)
#pragma unroll
                for (int nt = 0; nt < 4; nt++)
                    mma16816(c[mt][nt], afr[mt], bfr[nt]);
        }
    }

    const int er = lane >> 2;
    const int ec = (lane & 3) * 2;
#pragma unroll
    for (int mt = 0; mt < 4; mt++) {
#pragma unroll
        for (int nt = 0; nt < 4; nt++) {
            const int m = row0 + m0w + mt * 16 + er;
            const int n = col0 + n0w + nt * 8 + ec;
            const float b0 = __ldg(&bp[n]);
            const float b1 = __ldg(&bp[n + 1]);
            *reinterpret_cast<float2*>(&g_theta[(size_t)m * NTOT + n]) =
                make_float2(c[mt][nt][0] + b0, c[mt][nt][1] + b1);
            *reinterpret_cast<float2*>(&g_theta[(size_t)(m + 8) * NTOT + n]) =
                make_float2(c[mt][nt][2] + b0, c[mt][nt][3] + b1);
        }
    }
}

// ---------------------------------------------------------------------------
// Fused pair kernel: one block per b. (unchanged from R7)
// ---------------------------------------------------------------------------
__device__ __forceinline__ float sp_fast(float x) {
    return fmaxf(x, 0.0f) + __logf(1.0f + __expf(-fabsf(x)));
}
__device__ __forceinline__ int tri_S(int i) { return (i * (129 - i)) >> 1; }

__device__ __forceinline__ float dim1(float zi, float Zi, float zj, float Zj) {
    const float mz = fmaxf(zi, zj);
    const float mZ = fminf(Zi, Zj);
    const float u  = ex2f(C1EXP * fabsf(zi - zj));
    const float v  = ex2f(C1EXP * fabsf(Zi - Zj));
    const float L2 = lg2f((1.0f + u) * (1.0f + v));
    const float E  = ex2f(fmaf(mZ - mz, C2EXP, -0.2f * L2));
    return lg2f(1.0f + E);
}
__device__ __forceinline__ float quad(float4 zi, float4 Zi, float4 zj, float4 Zj) {
    return dim1(zi.x, Zi.x, zj.x, Zj.x) * dim1(zi.y, Zi.y, zj.y, Zj.y)
         * dim1(zi.z, Zi.z, zj.z, Zj.z) * dim1(zi.w, Zi.w, zj.w, Zj.w);
}
__device__ __forceinline__ float pairp(const float4* bi, const float4* bj) {
    return quad(bi[0], bi[2], bj[0], bj[2]) * quad(bi[1], bi[3], bj[1], bj[3]);
}

__global__ void __launch_bounds__(256) pair_kernel(const float* __restrict__ Wprob,
                                                   const float* __restrict__ bprob,
                                                   const float* __restrict__ Wrel,
                                                   const float* __restrict__ Wbox,
                                                   const float* __restrict__ bbox,
                                                   const float* __restrict__ brel,
                                                   float* __restrict__ out_concept,
                                                   float* __restrict__ out_cond,
                                                   float* __restrict__ out_task) {
    __shared__ float4 zZ4q[KC * 5];
    __shared__ float elvbC[KC];
    __shared__ float p_sh[KC];
    __shared__ float wrel_sh[KC * KC];
    __shared__ float wbox_sh[KC * 16];
    __shared__ float prod_sh[NPAIR];
    __shared__ float side_tmp[KC * DD];
    __shared__ float dot_tmp[KC * DD];
    __shared__ float red[256];

    const int b   = blockIdx.x;
    const int tid = threadIdx.x;
    float* zZf = reinterpret_cast<float*>(zZ4q);

    for (int idx = tid; idx < KC * KC; idx += 256) wrel_sh[idx] = Wrel[idx];
    for (int idx = tid; idx < KC * 16; idx += 256) wbox_sh[idx] = Wbox[idx];

    for (int u = tid; u < KC * DD; u += 256) {
        const int k = u >> 3, d = u & 7;
        const float* th = &g_theta[(size_t)b * NTOT + k * 16];
        const float z = th[d];
        const float Z = z + sp_fast(th[8 + d]);
        zZf[k * 20 + d]     = z;
        zZf[k * 20 + 8 + d] = Z;
        side_tmp[u] = 0.5f * sp_fast(2.0f * (Z - z));
        dot_tmp[u]  = z * __ldg(&Wprob[k * 16 + d]) + Z * __ldg(&Wprob[k * 16 + 8 + d]);
    }
    __syncthreads();

    if (tid < KC) {
        float pb = 1.0f;
        float lg = __ldg(&bprob[tid]);
#pragma unroll
        for (int d = 0; d < 8; d++) {
            pb *= side_tmp[tid * 8 + d];
            lg += dot_tmp[tid * 8 + d];
        }
        elvbC[tid] = C8 / pb;
        const float p = 1.0f / (1.0f + __expf(-lg));
        p_sh[tid] = p;
        out_concept[b * KC + tid] = p;
    }
    __syncthreads();

    for (int T = tid; T < NTILE; T += 256) {
        const int tt = T / 33;
        const int s  = T - tt * 33;
        int b2 = s + tt + 1;
        if (b2 >= 33) b2 -= 33;
        const int lo = min(s, b2), hi = max(s, b2);
        const int i0 = lo * 2;
        const int j0 = (hi - 1) * 2;

        float4 BI0[4], BI1[4], BJ0[4], BJ1[4];
#pragma unroll
        for (int r = 0; r < 4; r++) {
            BI0[r] = zZ4q[(i0 + 0) * 5 + r];
            BI1[r] = zZ4q[(i0 + 1) * 5 + r];
            BJ0[r] = zZ4q[(j0 + 0) * 5 + r];
            BJ1[r] = zZ4q[(j0 + 1) * 5 + r];
        }

        const float p00 = pairp(BI0, BJ0);
        const float p01 = pairp(BI0, BJ1);
        const float p11 = pairp(BI1, BJ1);

        const int q0 = tri_S(i0) + (j0 - i0);
        const int q1 = tri_S(i0 + 1) + (j0 - i0 - 1);
        prod_sh[q0]     = p00;
        prod_sh[q0 + 1] = p01;
        prod_sh[q1 + 1] = p11;
        if (i0 < j0) {
            prod_sh[q1] = pairp(BI1, BJ0);
        }
    }
    __syncthreads();

    float accrel = 0.0f;
#pragma unroll
    for (int g = 0; g < 4; g++) {
        const int idx = g * 1024 + tid * 4;
        const int i  = idx >> 6;
        const int jb = idx & 63;
        float4 cd;
        float* cdp = &cd.x;
#pragma unroll
        for (int r = 0; r < 4; r++) {
            const int j = jb + r;
            const int a = min(i, j), bq = max(i, j);
            const int q = tri_S(a) + (bq - a);
            float cc = prod_sh[q] * elvbC[j];
            cc = fminf(fmaxf(cc, 1e-6f), 1.0f - 1e-6f);
            cdp[r] = cc;
            accrel = fmaf(cc, wrel_sh[idx + r], accrel);
        }
        *reinterpret_cast<float4*>(&out_cond[(size_t)b * (KC * KC) + idx]) = cd;
    }

    red[tid] = accrel;
    __syncthreads();
    for (int s = 128; s > 0; s >>= 1) {
        if (tid < s) red[tid] += red[tid + s];
        __syncthreads();
    }
    const float reldot = red[0];
    __syncthreads();

    if (tid < KC) {
        float s = 0.0f;
#pragma unroll
        for (int d = 0; d < 8; d++) {
            s = fmaf(zZf[tid * 20 + d],     wbox_sh[tid * 16 + d],     s);
            s = fmaf(zZf[tid * 20 + 8 + d], wbox_sh[tid * 16 + 8 + d], s);
        }
        red[tid] = s * p_sh[tid];
    }
    __syncthreads();
    for (int s = 32; s > 0; s >>= 1) {
        if (tid < s) red[tid] += red[tid + s];
        __syncthreads();
    }

    if (tid == 0) {
        const float logit = red[0] + bbox[0] + reldot + brel[0];
        out_task[b] = 1.0f / (1.0f + expf(-logit));
    }
}

// ---------------------------------------------------------------------------
extern "C" void kernel_launch(void* const* d_in, const int* in_sizes, int n_in,
                              void* d_out, int out_size) {
    const float* features = (const float*)d_in[0];
    const float* Wp       = (const float*)d_in[1];
    const float* bp       = (const float*)d_in[2];
    const float* Wprob    = (const float*)d_in[3];
    const float* bprob    = (const float*)d_in[4];
    const float* Wbox     = (const float*)d_in[5];
    const float* bbox     = (const float*)d_in[6];
    const float* Wrel     = (const float*)d_in[7];
    const float* brel     = (const float*)d_in[8];

    float* out         = (float*)d_out;
    float* out_task    = out;
    float* out_concept = out + BSZ;
    float* out_cond    = out + BSZ + BSZ * KC;

    cudaFuncSetAttribute(gemm_hmma, cudaFuncAttributeMaxDynamicSharedMemorySize, SMEM_B);

    convA_kernel<<<(BSZ * (FDIM / 4) + 255) / 256, 256>>>(features);
    convB_kernel<<<(NTOT * (FDIM / 4) + 255) / 256, 256>>>(Wp);
    gemm_hmma<<<dim3(NTOT / TN, BSZ / TM), GT, SMEM_B>>>(bp);
    pair_kernel<<<BSZ, 256>>>(Wprob, bprob, Wrel, Wbox, bbox, brel,
                              out_concept, out_cond, out_task);
}